// round 5
// baseline (speedup 1.0000x reference)
#include <cuda_runtime.h>
#include <math.h>

#define N_ROWS 8192
#define T_COLS 256
#define NBLK   512          // 512 CTAs x 256 thr; 4/SM x 148 SM = 592 >= 512 (co-resident)

// Scratch (allocation-free __device__ globals; zero at load; every execution
// restores invariants => graph-replay safe)
__device__ float g_H[T_COLS * T_COLS];       // H[lab][dur] += ev_i * exp(-2*A_i)
__device__ float g_R[2 * T_COLS * T_COLS];   // R[2d+e][t]: e=0 sum_{d'<d}, e=1 sum_{d'<=d} of H[t][d']
__device__ float g_acc[2];                   // {nll_sum, rank_sum}
__device__ unsigned int g_tickets;
__device__ unsigned int g_gen;               // barrier generation (monotone across replays)
__device__ unsigned int g_cnt;               // barrier arrival counter

__device__ __forceinline__ float warp_max(float v) {
    #pragma unroll
    for (int o = 16; o > 0; o >>= 1) v = fmaxf(v, __shfl_xor_sync(0xffffffffu, v, o));
    return v;
}
__device__ __forceinline__ float warp_sum(float v) {
    #pragma unroll
    for (int o = 16; o > 0; o >>= 1) v += __shfl_xor_sync(0xffffffffu, v, o);
    return v;
}

// Grid-wide barrier; safe because all NBLK CTAs are co-resident.
__device__ __forceinline__ void grid_barrier() {
    __syncthreads();
    if (threadIdx.x == 0) {
        volatile unsigned int* vg = &g_gen;
        __threadfence();
        const unsigned int gen = *vg;
        if (atomicAdd(&g_cnt, 1u) == NBLK - 1u) {
            g_cnt = 0u;
            __threadfence();
            atomicAdd(&g_gen, 1u);
        } else {
            while (*vg == gen) { __nanosleep(32); }
        }
        __threadfence();
    }
    __syncthreads();
}

__global__ void __launch_bounds__(256, 4) fused_kernel(
    const float* __restrict__ hz,
    const int*   __restrict__ dur,
    const int*   __restrict__ ev,
    const int*   __restrict__ lab,
    float* __restrict__ out)
{
    __shared__ float2 sred[8];
    const int warp = threadIdx.x >> 5;
    const int lane = threadIdx.x & 31;
    const int gw   = blockIdx.x * 8 + warp;      // global warp: owns rows 2gw, 2gw+1

    // -------- Phase A: load + softmax scan, keep state in registers ---------
    float4 A4[2], B4[2];
    int   durv[2], evv[2], labv[2];
    #pragma unroll
    for (int r = 0; r < 2; r++) {
        const int row = gw * 2 + r;
        const float4* rp = reinterpret_cast<const float4*>(hz + (size_t)row * T_COLS);
        A4[r] = rp[lane * 2];
        B4[r] = rp[lane * 2 + 1];
        durv[r] = dur[row]; evv[r] = ev[row]; labv[r] = lab[row];
    }

    float scan[2][8];     // inclusive cumsum of exp(phi-gamma), lane-major
    float s2v[2];         // 2 / sum_
    float nllv[2];        // valid on all lanes
    int   kjv[2];

    #pragma unroll
    for (int r = 0; r < 2; r++) {
        float v[8] = {A4[r].x, A4[r].y, A4[r].z, A4[r].w,
                      B4[r].x, B4[r].y, B4[r].z, B4[r].w};
        float m = v[0];
        #pragma unroll
        for (int k = 1; k < 8; k++) m = fmaxf(m, v[k]);
        const float gamma = fmaxf(warp_max(m), 0.0f);   // pad column phi=0

        float e[8], local = 0.0f;
        #pragma unroll
        for (int k = 0; k < 8; k++) { e[k] = __expf(v[k] - gamma); local += e[k]; }

        float incl = local;
        #pragma unroll
        for (int o = 1; o < 32; o <<= 1) {
            float u = __shfl_up_sync(0xffffffffu, incl, o);
            if (lane >= o) incl += u;
        }
        const float total = __shfl_sync(0xffffffffu, incl, 31);
        float run = incl - local;

        const int L  = labv[r];
        const int kk = L & 7;
        float cum_sel = 0.0f, phi_sel = v[0];
        #pragma unroll
        for (int k = 0; k < 8; k++) {
            run += e[k];
            scan[r][k] = run;
            if (k == kk) { cum_sel = run; phi_sel = v[k]; }
        }
        const float cum_at = __shfl_sync(0xffffffffu, cum_sel, L >> 3);
        const float phi_at = __shfl_sync(0xffffffffu, phi_sel, L >> 3);

        const float sum_ = total + __expf(-gamma);
        s2v[r] = 2.0f / sum_;
        kjv[r] = 2 * durv[r] + ((evv[r] == 0) ? 1 : 0);

        const float EPS = 1e-7f;
        const float evf = (evv[r] != 0) ? 1.0f : 0.0f;
        const float part1 = (phi_at - gamma) * evf;
        const float part2 = -logf(fmaxf(sum_, 0.0f) + EPS);
        const float part3 = logf(fmaxf(sum_ - cum_at, 0.0f) + EPS) * (1.0f - evf);
        nllv[r] = -(part1 + part2 + part3);

        if (evv[r] != 0 && lane == 0)
            atomicAdd(&g_H[L * T_COLS + durv[r]], __expf(-2.0f * cum_at / sum_));
    }

    grid_barrier();

    // -------- Phase B: warps 0..255 -> column prefix H -> R, re-zero H ------
    if (gw < T_COLS) {
        const int t = gw;
        float4* hp = reinterpret_cast<float4*>(&g_H[t * T_COLS + lane * 8]);
        float4 h0 = hp[0], h1 = hp[1];
        float h[8] = {h0.x, h0.y, h0.z, h0.w, h1.x, h1.y, h1.z, h1.w};

        float local = 0.0f;
        #pragma unroll
        for (int k = 0; k < 8; k++) local += h[k];

        float incl = local;
        #pragma unroll
        for (int o = 1; o < 32; o <<= 1) {
            float u = __shfl_up_sync(0xffffffffu, incl, o);
            if (lane >= o) incl += u;
        }
        float run = incl - local;
        #pragma unroll
        for (int k = 0; k < 8; k++) {
            const int d = lane * 8 + k;
            g_R[(2 * d)     * T_COLS + t] = run;   // sum_{d'<d}
            run += h[k];
            g_R[(2 * d + 1) * T_COLS + t] = run;   // sum_{d'<=d}
        }
        hp[0] = make_float4(0.f, 0.f, 0.f, 0.f);   // restore invariant for replay
        hp[1] = make_float4(0.f, 0.f, 0.f, 0.f);
    }

    grid_barrier();

    // -------- Phase C: dot(R[kj], exp(scan*s2)) from registers --------------
    float rank = 0.0f;
    #pragma unroll
    for (int r = 0; r < 2; r++) {
        const float4* Rp = reinterpret_cast<const float4*>(g_R + (size_t)kjv[r] * T_COLS + lane * 8);
        float4 r0 = Rp[0], r1 = Rp[1];
        float rr[8] = {r0.x, r0.y, r0.z, r0.w, r1.x, r1.y, r1.z, r1.w};
        const float s2 = s2v[r];
        #pragma unroll
        for (int k = 0; k < 8; k++)
            rank += rr[k] * __expf(scan[r][k] * s2);
    }
    rank = warp_sum(rank);

    if (lane == 0) sred[warp] = make_float2(nllv[0] + nllv[1], rank);
    __syncthreads();

    if (threadIdx.x < 8) {
        float2 p = sred[threadIdx.x];
        #pragma unroll
        for (int o = 4; o > 0; o >>= 1) {
            p.x += __shfl_xor_sync(0xffu, p.x, o);
            p.y += __shfl_xor_sync(0xffu, p.y, o);
        }
        if (threadIdx.x == 0) {
            atomicAdd(&g_acc[0], p.x);
            atomicAdd(&g_acc[1], p.y);
            __threadfence();
            const unsigned int tk = atomicAdd(&g_tickets, 1u);
            if (tk == NBLK - 1u) {
                const float nll_sum  = atomicExch(&g_acc[0], 0.0f);
                const float rank_sum = atomicExch(&g_acc[1], 0.0f);
                const float ALPHA = 0.5f;
                out[0] = ALPHA * (nll_sum / (float)N_ROWS)
                       + (1.0f - ALPHA) * (rank_sum / ((float)N_ROWS * (float)N_ROWS));
                atomicExch(&g_tickets, 0u);
            }
        }
    }
}

extern "C" void kernel_launch(void* const* d_in, const int* in_sizes, int n_in,
                              void* d_out, int out_size)
{
    const float* hz  = (const float*)d_in[0];
    const int*   dur = (const int*)  d_in[1];
    const int*   ev  = (const int*)  d_in[2];
    const int*   lab = (const int*)  d_in[3];
    float* out = (float*)d_out;

    fused_kernel<<<NBLK, 256>>>(hz, dur, ev, lab, out);
}